// round 15
// baseline (speedup 1.0000x reference)
#include <cuda_runtime.h>
#include <cuda_bf16.h>
#include <math.h>
#include <stdint.h>

// ---------------- problem constants ----------------
#define VOCAB   100000
#define EMBED   300
#define HIDDEN  300
#define BATCH   32768
#define K_NEG   10
#define EPS_F   1e-5f

// ---------------- GEMM geometry ----------------
#define MTILE    128
#define MTILES   (BATCH / MTILE)        // 256
#define NSPLIT   5                      // N padded to 320, 64 per split
#define NCHK     5                      // K padded to 320, 64 per chunk
#define A_CHT_B  16384                  // A chunk tile: 128 rows * 128 B (bf16)
#define A_CHT_I4 1024
#define B_CHT_B  8192                   // B chunk tile: 64 rows * 128 B (bf16)
#define B_CHT_I4 512

// gemm1 dynamic smem layout
#define G1_A_OFF   0                    // 2 x 16384
#define G1_B_OFF   32768                // 2 x 8192
#define G1_ST_OFF  49152                // staging: 128 rows x 288 B
#define G1_ST_ROWB 288
#define G1_SMEM    (G1_ST_OFF + 128 * G1_ST_ROWB)   // 86016

#define NPART 4096

// ---------------- scratch (device globals; no allocation allowed) ----------------
__device__ int4  g_a2[MTILES * NCHK * A_CHT_I4];   // enc, bf16 swizzled (GEMM1 epilogue)
__device__ int4  g_w1[NSPLIT * NCHK * B_CHT_I4];   // [W_enc; W_cls; 0] bf16 swizzled
__device__ int4  g_w2[NSPLIT * NCHK * B_CHT_I4];   // [W_dec; 0] bf16 swizzled
__device__ float g_logits[BATCH * 2];
__device__ __nv_bfloat16 g_cv[BATCH * EMBED];      // center_v in bf16
__device__ float2 g_partial[NPART];

// ---------------- small device helpers ----------------
__device__ __forceinline__ uint32_t swz(uint32_t o) { return o ^ ((o >> 3) & 0x70); }

__device__ __forceinline__ uint32_t smem_u32(const void* p) {
    uint32_t a;
    asm("{ .reg .u64 t; cvta.to.shared.u64 t, %1; cvt.u32.u64 %0, t; }" : "=r"(a) : "l"(p));
    return a;
}
__device__ __forceinline__ void ldm_x4(uint32_t* r, uint32_t addr) {
    asm volatile("ldmatrix.sync.aligned.m8n8.x4.shared.b16 {%0,%1,%2,%3}, [%4];"
                 : "=r"(r[0]), "=r"(r[1]), "=r"(r[2]), "=r"(r[3]) : "r"(addr));
}
__device__ __forceinline__ void mma_16816(float* c, const uint32_t* a, const uint32_t* b) {
    asm volatile("mma.sync.aligned.m16n8k16.row.col.f32.bf16.bf16.f32 "
                 "{%0,%1,%2,%3}, {%4,%5,%6,%7}, {%8,%9}, {%0,%1,%2,%3};"
                 : "+f"(c[0]), "+f"(c[1]), "+f"(c[2]), "+f"(c[3])
                 : "r"(a[0]), "r"(a[1]), "r"(a[2]), "r"(a[3]), "r"(b[0]), "r"(b[1]));
}
__device__ __forceinline__ void cp_async16(uint32_t dst, const void* src) {
    asm volatile("cp.async.cg.shared.global [%0], [%1], 16;" :: "r"(dst), "l"(src));
}
__device__ __forceinline__ void cp_async16p(uint32_t dst, const void* src, bool pred) {
    if (pred)
        asm volatile("cp.async.cg.shared.global [%0], [%1], 16;" :: "r"(dst), "l"(src));
}
__device__ __forceinline__ void cp_commit() {
    asm volatile("cp.async.commit_group;" ::: "memory");
}
__device__ __forceinline__ void cp_wait0() {
    asm volatile("cp.async.wait_group 0;" ::: "memory");
}

__device__ __forceinline__ int4 pack8_bf16(const float* v) {
    union { __nv_bfloat162 h[4]; int4 q; } u;
#pragma unroll
    for (int j = 0; j < 4; j++) u.h[j] = __floats2bfloat162_rn(v[2 * j], v[2 * j + 1]);
    return u.q;
}

// ---------------------------------------------------------------------------
// Prepass W: both weight conversions in one launch (vectorized by 8).
// mode 0 (-> g_w1): rows 0..299 = W_enc, 300..301 = W_cls, rest 0
// mode 1 (-> g_w2): rows 0..299 = W_dec, rest 0
// ---------------------------------------------------------------------------
__global__ __launch_bounds__(256)
void conv_w_kernel(const float* __restrict__ Wenc, const float* __restrict__ Wcls,
                   const float* __restrict__ Wdec)
{
    const int PER_MODE = NSPLIT * NCHK * 64 * 8;   // 12800 groups
    int idx = blockIdx.x * blockDim.x + threadIdx.x;
    if (idx >= 2 * PER_MODE) return;
    int mode = idx / PER_MODE;
    int rem  = idx - mode * PER_MODE;
    int col8 = rem & 7;
    int r    = (rem >> 3) & 63;
    int t    = rem >> 9;
    int c    = t % NCHK;
    int s    = t / NCHK;
    int n  = s * 64 + r;
    int k0 = c * 64 + col8 * 8;

    const float* row = nullptr;
    if (n < 300) row = (mode == 0 ? Wenc : Wdec) + (long)n * 300;
    else if (mode == 0 && n < 302) row = Wcls + (long)(n - 300) * 300;

    float v[8];
#pragma unroll
    for (int j = 0; j < 8; j++) v[j] = 0.f;
    if (row) {
        if (k0 + 8 <= 300) {
            float4 f0 = *(const float4*)(row + k0);
            float4 f1 = *(const float4*)(row + k0 + 4);
            v[0]=f0.x; v[1]=f0.y; v[2]=f0.z; v[3]=f0.w;
            v[4]=f1.x; v[5]=f1.y; v[6]=f1.z; v[7]=f1.w;
        } else if (k0 < 300) {
            float4 f0 = *(const float4*)(row + k0);
            v[0]=f0.x; v[1]=f0.y; v[2]=f0.z; v[3]=f0.w;
        }
    }
    int4* gw = (mode == 0) ? g_w1 : g_w2;
    char* base = (char*)gw + (size_t)(s * NCHK + c) * B_CHT_B;
    *(int4*)(base + swz((uint32_t)(r * 128 + (k0 & 63) * 2))) = pack8_bf16(v);
}

// ---------------------------------------------------------------------------
// GEMM1 (fused gather): C[128,64] = center_emb[ids][128,320] @ W1[64,320]^T
// A gathered as f32 via cp.async into padded staging, converted to bf16
// swizzled tiles in-kernel. One barrier per chunk.
// Epilogue: g_a2 bf16 swizzled (+bias) and g_logits for n==300/301 (+b_cls).
// ---------------------------------------------------------------------------
__global__ __launch_bounds__(256)
void gemm1_kernel(const float* __restrict__ emb, const int* __restrict__ ids,
                  const int4* __restrict__ B,
                  const float* __restrict__ bias, const float* __restrict__ bias2)
{
    extern __shared__ char smem[];
    const uint32_t sbase = smem_u32(smem);

    const int tid  = threadIdx.x;
    const int wid  = tid >> 5;
    const int lane = tid & 31;
    const int mt = blockIdx.y;
    const int ns = blockIdx.x;
    const int mw = wid & 3;
    const int nw = wid >> 2;

    // loader identity: 2 threads per A row
    const int lrow = tid >> 1;          // 0..127
    const int half = tid & 1;           // 0/1 -> k cols 0..31 / 32..63
    const float* rowp = emb + (size_t)ids[mt * MTILE + lrow] * EMBED;
    const uint32_t st_my = sbase + G1_ST_OFF + (uint32_t)lrow * G1_ST_ROWB + half * 144u;
    char* st_myp = smem + G1_ST_OFF + lrow * G1_ST_ROWB + half * 144;

    float acc[2][4][4];
#pragma unroll
    for (int i = 0; i < 2; i++)
#pragma unroll
        for (int j = 0; j < 4; j++)
#pragma unroll
            for (int q = 0; q < 4; q++) acc[i][j][q] = 0.f;

    const int4* Bbase = B + (size_t)ns * NCHK * B_CHT_I4;

    const uint32_t a_row  = mw * 32 + (lane & 15);
    const uint32_t a_kb   = (lane >> 4) * 16;
    const uint32_t b_row  = nw * 32 + (lane & 7) + ((lane >> 4) << 3);
    const uint32_t b_kb   = ((lane >> 3) & 1) * 16;

#define PRE1(c) do {                                                           \
        const float* _src = rowp + (c) * 64 + half * 32;                       \
        _Pragma("unroll")                                                      \
        for (int _j = 0; _j < 8; _j++)                                         \
            cp_async16p(st_my + _j * 16u, _src + _j * 4,                       \
                        ((c) < 4) || (half == 0) || (_j < 3));                 \
        const int4* _bs = Bbase + (c) * B_CHT_I4;                              \
        uint32_t _db = sbase + G1_B_OFF + (uint32_t)(((c) & 1) * B_CHT_B);     \
        cp_async16(_db + (uint32_t)tid * 16u, _bs + tid);                      \
        cp_async16(_db + (uint32_t)(tid + 256) * 16u, _bs + tid + 256);        \
        cp_commit();                                                           \
    } while (0)

    PRE1(0);

    for (int c = 0; c < NCHK; c++) {
        cp_wait0();   // this thread's staging(c) + B(c) complete

        // convert own staging slots -> bf16 swizzled A tile [c&1]
        {
            char* at = smem + ((c & 1) ? A_CHT_B : 0);
#pragma unroll
            for (int q = 0; q < 4; q++) {
                float4 f0 = *(const float4*)(st_myp + q * 32);
                float4 f1 = *(const float4*)(st_myp + q * 32 + 16);
                float v[8] = { f0.x, f0.y, f0.z, f0.w, f1.x, f1.y, f1.z, f1.w };
                int col0 = half * 32 + q * 8;
                *(int4*)(at + swz((uint32_t)(lrow * 128 + col0 * 2))) = pack8_bf16(v);
            }
        }
        __syncthreads();   // A,B visible to all; prior-chunk MMAs done
        if (c + 1 < NCHK) PRE1(c + 1);

        const uint32_t aB = sbase + (uint32_t)((c & 1) ? A_CHT_B : 0);
        const uint32_t bB = sbase + G1_B_OFF + (uint32_t)((c & 1) * B_CHT_B);
#pragma unroll
        for (int ks = 0; ks < 4; ks++) {
            const uint32_t kb = ks * 32;
            uint32_t a[2][4];
#pragma unroll
            for (int fm = 0; fm < 2; fm++)
                ldm_x4(a[fm], aB + swz((a_row + fm * 16) * 128 + kb + a_kb));
#pragma unroll
            for (int p = 0; p < 2; p++) {
                uint32_t bq[4];
                ldm_x4(bq, bB + swz((b_row + p * 16) * 128 + kb + b_kb));
                mma_16816(acc[0][2 * p + 0], a[0], bq + 0);
                mma_16816(acc[1][2 * p + 0], a[1], bq + 0);
                mma_16816(acc[0][2 * p + 1], a[0], bq + 2);
                mma_16816(acc[1][2 * p + 1], a[1], bq + 2);
            }
        }
    }
#undef PRE1

    // ---- epilogue: enc -> g_a2 (bf16 swizzled) + logits ----
#pragma unroll
    for (int fm = 0; fm < 2; fm++) {
#pragma unroll
        for (int fn = 0; fn < 4; fn++) {
            const int n = ns * 64 + nw * 32 + fn * 8 + 2 * (lane & 3);
#pragma unroll
            for (int hh = 0; hh < 2; hh++) {
                const int mrow = mw * 32 + fm * 16 + (lane >> 2) + hh * 8;
                const long m = (long)mt * MTILE + mrow;
                float v0 = acc[fm][fn][hh * 2 + 0];
                float v1 = acc[fm][fn][hh * 2 + 1];
                float b0 = (n < 300) ? bias[n] : ((n == 300) ? bias2[0] : 0.f);
                float b1 = (n + 1 < 300) ? bias[n + 1] : ((n + 1 == 301) ? bias2[1] : 0.f);
                v0 += b0; v1 += b1;
                if (n == 300) {
                    g_logits[m * 2 + 0] = v0;
                    g_logits[m * 2 + 1] = v1;
                }
                __nv_bfloat162 h = __floats2bfloat162_rn(v0, v1);
                char* dst = (char*)g_a2 + (size_t)(mt * NCHK + ns) * A_CHT_B
                            + swz((uint32_t)(mrow * 128 + (n & 63) * 2));
                *(__nv_bfloat162*)dst = h;
            }
        }
    }
}

// ---------------------------------------------------------------------------
// GEMM2: cv = enc @ W_dec^T + b_dec. A pre-swizzled bf16 (g_a2), cp.async
// double-buffered, single barrier per chunk. Output g_cv bf16.
// ---------------------------------------------------------------------------
__global__ __launch_bounds__(256)
void gemm2_kernel(const int4* __restrict__ A, const int4* __restrict__ B,
                  const float* __restrict__ bias)
{
    __shared__ int4 smem2[2 * A_CHT_I4 + 2 * B_CHT_I4];   // 48 KB
    const uint32_t sbase = smem_u32(smem2);
    const uint32_t sAoff[2] = { 0u, (uint32_t)A_CHT_B };
    const uint32_t sBoff[2] = { 2u * A_CHT_B, 2u * A_CHT_B + B_CHT_B };

    const int tid  = threadIdx.x;
    const int wid  = tid >> 5;
    const int lane = tid & 31;
    const int mt = blockIdx.y;
    const int ns = blockIdx.x;
    const int mw = wid & 3;
    const int nw = wid >> 2;

    float acc[2][4][4];
#pragma unroll
    for (int i = 0; i < 2; i++)
#pragma unroll
        for (int j = 0; j < 4; j++)
#pragma unroll
            for (int q = 0; q < 4; q++) acc[i][j][q] = 0.f;

    const int4* Abase = A + (size_t)mt * NCHK * A_CHT_I4;
    const int4* Bbase = B + (size_t)ns * NCHK * B_CHT_I4;

    const uint32_t a_row  = mw * 32 + (lane & 15);
    const uint32_t a_kb   = (lane >> 4) * 16;
    const uint32_t b_row  = nw * 32 + (lane & 7) + ((lane >> 4) << 3);
    const uint32_t b_kb   = ((lane >> 3) & 1) * 16;

#define PRE2(c, buf) do {                                                      \
        const int4* _as = Abase + (c) * A_CHT_I4;                              \
        uint32_t _da = sbase + sAoff[buf];                                     \
        _Pragma("unroll")                                                      \
        for (int _i = 0; _i < 4; _i++)                                         \
            cp_async16(_da + (uint32_t)(tid + _i * 256) * 16u, _as + tid + _i * 256); \
        const int4* _bs = Bbase + (c) * B_CHT_I4;                              \
        uint32_t _db = sbase + sBoff[buf];                                     \
        _Pragma("unroll")                                                      \
        for (int _i = 0; _i < 2; _i++)                                         \
            cp_async16(_db + (uint32_t)(tid + _i * 256) * 16u, _bs + tid + _i * 256); \
        cp_commit();                                                           \
    } while (0)

    PRE2(0, 0);

    for (int c = 0; c < NCHK; c++) {
        cp_wait0();
        __syncthreads();
        if (c + 1 < NCHK) PRE2(c + 1, (c + 1) & 1);

        const uint32_t aB = sbase + sAoff[c & 1];
        const uint32_t bB = sbase + sBoff[c & 1];
#pragma unroll
        for (int ks = 0; ks < 4; ks++) {
            const uint32_t kb = ks * 32;
            uint32_t a[2][4];
#pragma unroll
            for (int fm = 0; fm < 2; fm++)
                ldm_x4(a[fm], aB + swz((a_row + fm * 16) * 128 + kb + a_kb));
#pragma unroll
            for (int p = 0; p < 2; p++) {
                uint32_t bq[4];
                ldm_x4(bq, bB + swz((b_row + p * 16) * 128 + kb + b_kb));
                mma_16816(acc[0][2 * p + 0], a[0], bq + 0);
                mma_16816(acc[1][2 * p + 0], a[1], bq + 0);
                mma_16816(acc[0][2 * p + 1], a[0], bq + 2);
                mma_16816(acc[1][2 * p + 1], a[1], bq + 2);
            }
        }
    }
#undef PRE2

    // ---- epilogue: cv bf16 ----
#pragma unroll
    for (int fm = 0; fm < 2; fm++) {
#pragma unroll
        for (int fn = 0; fn < 4; fn++) {
            const int n = ns * 64 + nw * 32 + fn * 8 + 2 * (lane & 3);
            if (n >= 300) continue;    // n even => n <= 298
#pragma unroll
            for (int hh = 0; hh < 2; hh++) {
                const int mrow = mw * 32 + fm * 16 + (lane >> 2) + hh * 8;
                const long m = (long)mt * MTILE + mrow;
                float v0 = acc[fm][fn][hh * 2 + 0] + bias[n];
                float v1 = acc[fm][fn][hh * 2 + 1] + bias[n + 1];
                *(__nv_bfloat162*)(g_cv + m * EMBED + n) = __floats2bfloat162_rn(v0, v1);
            }
        }
    }
}

// ---------------------------------------------------------------------------
// math helpers
// ---------------------------------------------------------------------------
__device__ __forceinline__ float softplus_f(float x) {
    float ax = fabsf(x);
    float r = log1pf(__expf(-ax));
    return (x > 0.f) ? x + r : r;
}
__device__ __forceinline__ float clip10(float x) { return fminf(fmaxf(x, -10.f), 10.f); }
__device__ __forceinline__ float warp_sum(float v) {
#pragma unroll
    for (int o = 16; o > 0; o >>= 1) v += __shfl_xor_sync(0xffffffffu, v, o);
    return v;
}

// ---------------------------------------------------------------------------
// Score: one warp per sample, full-ILP gathers, deterministic block partials.
// ---------------------------------------------------------------------------
__global__ __launch_bounds__(256)
void score_kernel(const int* __restrict__ ctx_ids,
                  const int* __restrict__ neg_ids,
                  const int* __restrict__ party,
                  const float* __restrict__ ctx_emb)
{
    const int warp = threadIdx.x >> 5;
    const int lane = threadIdx.x & 31;
    const int b    = blockIdx.x * 8 + warp;

    __shared__ float s_deno[8];
    __shared__ float s_cono[8];

    float2 cv[5];
    const __nv_bfloat162* cvrow = (const __nv_bfloat162*)(g_cv + (long)b * EMBED);
#pragma unroll
    for (int j = 0; j < 5; j++) {
        int e2 = lane + j * 32;
        cv[j] = (e2 < 150) ? __bfloat1622float2(cvrow[e2]) : make_float2(0.f, 0.f);
    }

    const float2* rows[11];
    rows[0] = (const float2*)(ctx_emb + (long)ctx_ids[b] * EMBED);
#pragma unroll
    for (int k = 0; k < K_NEG; k++)
        rows[1 + k] = (const float2*)(ctx_emb + (long)neg_ids[b * K_NEG + k] * EMBED);

    float s[11];
#pragma unroll
    for (int r = 0; r < 11; r++) s[r] = 0.f;

#pragma unroll
    for (int j = 0; j < 5; j++) {
        int e2 = lane + j * 32;
        if (e2 < 150) {
#pragma unroll
            for (int r = 0; r < 11; r++) {
                float2 t = rows[r][e2];
                s[r] = fmaf(cv[j].x, t.x, fmaf(cv[j].y, t.y, s[r]));
            }
        }
    }

#pragma unroll
    for (int r = 0; r < 11; r++) s[r] = warp_sum(s[r]);

    float deno = softplus_f(-clip10(s[0]));
#pragma unroll
    for (int r = 1; r < 11; r++) deno += softplus_f(clip10(s[r]));

    float l0 = g_logits[b * 2 + 0];
    float l1 = g_logits[b * 2 + 1];
    int lab = party[b];
    float nll = softplus_f((lab == 0) ? (l1 - l0) : (l0 - l1));

    if (lane == 0) { s_deno[warp] = deno; s_cono[warp] = nll; }
    __syncthreads();
    if (threadIdx.x == 0) {
        float ds = 0.f, cs = 0.f;
#pragma unroll
        for (int w = 0; w < 8; w++) { ds += s_deno[w]; cs += s_cono[w]; }
        g_partial[blockIdx.x] = make_float2(ds, cs);
    }
}

// ---------------------------------------------------------------------------
// Finalize
// ---------------------------------------------------------------------------
__global__ __launch_bounds__(1024)
void finalize_kernel(float* __restrict__ out)
{
    __shared__ float sd[1024];
    __shared__ float sc[1024];
    float d = 0.f, c = 0.f;
    for (int i = threadIdx.x; i < NPART; i += 1024) {
        float2 p = g_partial[i];
        d += p.x; c += p.y;
    }
    sd[threadIdx.x] = d; sc[threadIdx.x] = c;
    __syncthreads();
    for (int s = 512; s > 0; s >>= 1) {
        if (threadIdx.x < s) {
            sd[threadIdx.x] += sd[threadIdx.x + s];
            sc[threadIdx.x] += sc[threadIdx.x + s];
        }
        __syncthreads();
    }
    if (threadIdx.x == 0) {
        float dn = sd[0] / (float)BATCH;
        float cn = sc[0] / (float)BATCH;
        dn = fminf(fmaxf(dn, EPS_F), 10.f);
        cn = fminf(fmaxf(cn, EPS_F), 10.f);
        out[0] = fmaxf(dn + cn, EPS_F);
        out[1] = dn;
        out[2] = cn;
    }
}

// ---------------------------------------------------------------------------
// kernel_launch
// ---------------------------------------------------------------------------
extern "C" void kernel_launch(void* const* d_in, const int* in_sizes, int n_in,
                              void* d_out, int out_size)
{
    const int*   center_ids = (const int*)  d_in[0];
    const int*   ctx_ids    = (const int*)  d_in[1];
    const int*   neg_ids    = (const int*)  d_in[2];
    const int*   party      = (const int*)  d_in[3];
    const float* center_emb = (const float*)d_in[4];
    const float* ctx_emb    = (const float*)d_in[5];
    const float* W_enc      = (const float*)d_in[6];
    const float* b_enc      = (const float*)d_in[7];
    const float* W_dec      = (const float*)d_in[8];
    const float* b_dec      = (const float*)d_in[9];
    const float* W_cls      = (const float*)d_in[10];
    const float* b_cls      = (const float*)d_in[11];
    float* out = (float*)d_out;

    int4 *a2, *w1, *w2;
    cudaGetSymbolAddress((void**)&a2, g_a2);
    cudaGetSymbolAddress((void**)&w1, g_w1);
    cudaGetSymbolAddress((void**)&w2, g_w2);

    // allow 84 KB dynamic smem for gemm1 (idempotent; not a stream op)
    cudaFuncSetAttribute(gemm1_kernel, cudaFuncAttributeMaxDynamicSharedMemorySize,
                         G1_SMEM);

    // prepass: weights only (A gather fused into gemm1)
    conv_w_kernel<<<(2 * NSPLIT * NCHK * 64 * 8 + 255) / 256, 256>>>(W_enc, W_cls, W_dec);

    // GEMM1: [enc | logits] = gather(center_emb) @ [W_enc; W_cls]^T
    gemm1_kernel<<<dim3(NSPLIT, MTILES), 256, G1_SMEM>>>(center_emb, center_ids,
                                                         w1, b_enc, b_cls);
    // GEMM2: cv = enc @ W_dec^T + b_dec
    gemm2_kernel<<<dim3(NSPLIT, MTILES), 256>>>(a2, w2, b_dec);

    // scoring + reduction
    score_kernel<<<NPART, 256>>>(ctx_ids, neg_ids, party, ctx_emb);
    finalize_kernel<<<1, 1024>>>(out);
}

// round 16
// speedup vs baseline: 1.2495x; 1.2495x over previous
#include <cuda_runtime.h>
#include <cuda_bf16.h>
#include <math.h>
#include <stdint.h>

// ---------------- problem constants ----------------
#define VOCAB   100000
#define EMBED   300
#define HIDDEN  300
#define BATCH   32768
#define K_NEG   10
#define EPS_F   1e-5f

// ---------------- GEMM geometry ----------------
#define MTILE    128
#define MTILES   (BATCH / MTILE)        // 256
#define NSPLIT   5                      // N padded to 320, 64 per split
#define NCHK     5                      // K padded to 320, 64 per chunk
#define A_CHT_B  16384                  // A chunk tile: 128 rows * 128 B
#define A_CHT_I4 1024
#define B_CHT_B  8192                   // B chunk tile: 64 rows * 128 B
#define B_CHT_I4 512

#define NPART 4096

// ---------------- scratch (device globals; no allocation allowed) ----------------
__device__ int4  g_a1[MTILES * NCHK * A_CHT_I4];   // gathered center_emb, bf16 swizzled
__device__ int4  g_a2[MTILES * NCHK * A_CHT_I4];   // enc, bf16 swizzled (GEMM1 epilogue)
__device__ int4  g_w1[NSPLIT * NCHK * B_CHT_I4];   // [W_enc; W_cls; 0] bf16 swizzled
__device__ int4  g_w2[NSPLIT * NCHK * B_CHT_I4];   // [W_dec; 0] bf16 swizzled
__device__ float g_logits[BATCH * 2];
__device__ __nv_bfloat16 g_cv[BATCH * EMBED];      // center_v in bf16
__device__ float2 g_partial[NPART];

// ---------------- small device helpers ----------------
__device__ __forceinline__ uint32_t swz(uint32_t o) { return o ^ ((o >> 3) & 0x70); }

__device__ __forceinline__ uint32_t smem_u32(const void* p) {
    uint32_t a;
    asm("{ .reg .u64 t; cvta.to.shared.u64 t, %1; cvt.u32.u64 %0, t; }" : "=r"(a) : "l"(p));
    return a;
}
__device__ __forceinline__ void ldm_x4(uint32_t* r, uint32_t addr) {
    asm volatile("ldmatrix.sync.aligned.m8n8.x4.shared.b16 {%0,%1,%2,%3}, [%4];"
                 : "=r"(r[0]), "=r"(r[1]), "=r"(r[2]), "=r"(r[3]) : "r"(addr));
}
__device__ __forceinline__ void mma_16816(float* c, const uint32_t* a, const uint32_t* b) {
    asm volatile("mma.sync.aligned.m16n8k16.row.col.f32.bf16.bf16.f32 "
                 "{%0,%1,%2,%3}, {%4,%5,%6,%7}, {%8,%9}, {%0,%1,%2,%3};"
                 : "+f"(c[0]), "+f"(c[1]), "+f"(c[2]), "+f"(c[3])
                 : "r"(a[0]), "r"(a[1]), "r"(a[2]), "r"(a[3]), "r"(b[0]), "r"(b[1]));
}
__device__ __forceinline__ void cp_async16(uint32_t dst, const void* src) {
    asm volatile("cp.async.cg.shared.global [%0], [%1], 16;" :: "r"(dst), "l"(src));
}
__device__ __forceinline__ void cp_commit() {
    asm volatile("cp.async.commit_group;" ::: "memory");
}
__device__ __forceinline__ void cp_wait0() {
    asm volatile("cp.async.wait_group 0;" ::: "memory");
}

__device__ __forceinline__ int4 pack8_bf16(const float* v) {
    union { __nv_bfloat162 h[4]; int4 q; } u;
#pragma unroll
    for (int j = 0; j < 4; j++) u.h[j] = __floats2bfloat162_rn(v[2 * j], v[2 * j + 1]);
    return u.q;
}

// ---------------------------------------------------------------------------
// Prepass A: gather center_emb rows -> bf16 swizzled chunk tiles.
// One thread = 8 consecutive k (2x float4 load, 1x int4 swizzled store).
// ---------------------------------------------------------------------------
__global__ __launch_bounds__(256)
void conv_a_kernel(const float* __restrict__ emb, const int* __restrict__ ids)
{
    int idx = blockIdx.x * blockDim.x + threadIdx.x;   // BATCH*40 threads
    int m  = idx / 40;
    int g  = idx - m * 40;
    int k0 = g * 8;
    const float* row = emb + (long)ids[m] * EMBED;

    float v[8];
    if (k0 + 8 <= EMBED) {
        float4 f0 = *(const float4*)(row + k0);
        float4 f1 = *(const float4*)(row + k0 + 4);
        v[0]=f0.x; v[1]=f0.y; v[2]=f0.z; v[3]=f0.w;
        v[4]=f1.x; v[5]=f1.y; v[6]=f1.z; v[7]=f1.w;
    } else if (k0 < EMBED) {      // k0 == 296
        float4 f0 = *(const float4*)(row + k0);
        v[0]=f0.x; v[1]=f0.y; v[2]=f0.z; v[3]=f0.w;
        v[4]=v[5]=v[6]=v[7]=0.f;
    } else {
#pragma unroll
        for (int j = 0; j < 8; j++) v[j] = 0.f;
    }

    int mt = m >> 7, mrow = m & 127, ch = k0 >> 6, col0 = k0 & 63;
    char* base = (char*)g_a1 + (size_t)(mt * NCHK + ch) * A_CHT_B;
    *(int4*)(base + swz((uint32_t)(mrow * 128 + col0 * 2))) = pack8_bf16(v);
}

// ---------------------------------------------------------------------------
// Prepass W: both weight conversions in one launch (vectorized by 8).
// mode 0 (-> g_w1): rows 0..299 = W_enc, 300..301 = W_cls, rest 0
// mode 1 (-> g_w2): rows 0..299 = W_dec, rest 0
// ---------------------------------------------------------------------------
__global__ __launch_bounds__(256)
void conv_w_kernel(const float* __restrict__ Wenc, const float* __restrict__ Wcls,
                   const float* __restrict__ Wdec)
{
    const int PER_MODE = NSPLIT * NCHK * 64 * 8;   // 12800 groups
    int idx = blockIdx.x * blockDim.x + threadIdx.x;
    if (idx >= 2 * PER_MODE) return;
    int mode = idx / PER_MODE;
    int rem  = idx - mode * PER_MODE;
    int col8 = rem & 7;
    int r    = (rem >> 3) & 63;
    int t    = rem >> 9;
    int c    = t % NCHK;
    int s    = t / NCHK;
    int n  = s * 64 + r;
    int k0 = c * 64 + col8 * 8;

    const float* row = nullptr;
    if (n < 300) row = (mode == 0 ? Wenc : Wdec) + (long)n * 300;
    else if (mode == 0 && n < 302) row = Wcls + (long)(n - 300) * 300;

    float v[8];
#pragma unroll
    for (int j = 0; j < 8; j++) v[j] = 0.f;
    if (row) {
        if (k0 + 8 <= 300) {
            float4 f0 = *(const float4*)(row + k0);
            float4 f1 = *(const float4*)(row + k0 + 4);
            v[0]=f0.x; v[1]=f0.y; v[2]=f0.z; v[3]=f0.w;
            v[4]=f1.x; v[5]=f1.y; v[6]=f1.z; v[7]=f1.w;
        } else if (k0 < 300) {
            float4 f0 = *(const float4*)(row + k0);
            v[0]=f0.x; v[1]=f0.y; v[2]=f0.z; v[3]=f0.w;
        }
    }
    int4* gw = (mode == 0) ? g_w1 : g_w2;
    char* base = (char*)gw + (size_t)(s * NCHK + c) * B_CHT_B;
    *(int4*)(base + swz((uint32_t)(r * 128 + (k0 & 63) * 2))) = pack8_bf16(v);
}

// ---------------------------------------------------------------------------
// bf16 HMMA GEMM, cp.async double-buffered, ONE sync per chunk:
//   wait_group 0 -> __syncthreads -> prefetch(c+1) -> compute(c)
// mode 1: epilogue -> g_a2 (bf16 swizzled A-layout) + g_logits (+b_cls)
// mode 2: epilogue -> g_cv bf16 (+b_dec)
// ---------------------------------------------------------------------------
__global__ __launch_bounds__(256)
void gemm_kernel(const int4* __restrict__ A, const int4* __restrict__ B,
                 const float* __restrict__ bias, const float* __restrict__ bias2,
                 int mode)
{
    __shared__ int4 smem[2 * A_CHT_I4 + 2 * B_CHT_I4];   // 48 KB
    const uint32_t sbase = smem_u32(smem);
    const uint32_t sAoff[2] = { 0u, (uint32_t)A_CHT_B };
    const uint32_t sBoff[2] = { 2u * A_CHT_B, 2u * A_CHT_B + B_CHT_B };

    const int tid  = threadIdx.x;
    const int wid  = tid >> 5;
    const int lane = tid & 31;
    const int mt = blockIdx.y;
    const int ns = blockIdx.x;
    const int mw = wid & 3;          // M quarter (32 rows)
    const int nw = wid >> 2;         // N half   (32 cols)

    float acc[2][4][4];
#pragma unroll
    for (int i = 0; i < 2; i++)
#pragma unroll
        for (int j = 0; j < 4; j++)
#pragma unroll
            for (int q = 0; q < 4; q++) acc[i][j][q] = 0.f;

    const int4* Abase = A + (size_t)mt * NCHK * A_CHT_I4;
    const int4* Bbase = B + (size_t)ns * NCHK * B_CHT_I4;

    const uint32_t a_row  = mw * 32 + (lane & 15);
    const uint32_t a_kb   = (lane >> 4) * 16;
    const uint32_t b_row  = nw * 32 + (lane & 7) + ((lane >> 4) << 3);
    const uint32_t b_kb   = ((lane >> 3) & 1) * 16;

#define PREFETCH(c, buf) do {                                                  \
        const int4* _as = Abase + (c) * A_CHT_I4;                              \
        uint32_t _da = sbase + sAoff[buf];                                     \
        _Pragma("unroll")                                                      \
        for (int _i = 0; _i < 4; _i++)                                         \
            cp_async16(_da + (uint32_t)(tid + _i * 256) * 16u, _as + tid + _i * 256); \
        const int4* _bs = Bbase + (c) * B_CHT_I4;                              \
        uint32_t _db = sbase + sBoff[buf];                                     \
        _Pragma("unroll")                                                      \
        for (int _i = 0; _i < 2; _i++)                                         \
            cp_async16(_db + (uint32_t)(tid + _i * 256) * 16u, _bs + tid + _i * 256); \
        cp_commit();                                                           \
    } while (0)

    PREFETCH(0, 0);

    for (int c = 0; c < NCHK; c++) {
        cp_wait0();          // chunk c resident
        __syncthreads();     // all warps past chunk c-1 compute; smem visible
        if (c + 1 < NCHK) PREFETCH(c + 1, (c + 1) & 1);   // overlaps MMAs below

        const uint32_t aB = sbase + sAoff[c & 1];
        const uint32_t bB = sbase + sBoff[c & 1];
#pragma unroll
        for (int ks = 0; ks < 4; ks++) {
            const uint32_t kb = ks * 32;
            uint32_t a[2][4];
#pragma unroll
            for (int fm = 0; fm < 2; fm++)
                ldm_x4(a[fm], aB + swz((a_row + fm * 16) * 128 + kb + a_kb));
#pragma unroll
            for (int p = 0; p < 2; p++) {
                uint32_t bq[4];
                ldm_x4(bq, bB + swz((b_row + p * 16) * 128 + kb + b_kb));
                mma_16816(acc[0][2 * p + 0], a[0], bq + 0);
                mma_16816(acc[1][2 * p + 0], a[1], bq + 0);
                mma_16816(acc[0][2 * p + 1], a[0], bq + 2);
                mma_16816(acc[1][2 * p + 1], a[1], bq + 2);
            }
        }
    }
#undef PREFETCH

    // ---- epilogue (registers only) ----
#pragma unroll
    for (int fm = 0; fm < 2; fm++) {
#pragma unroll
        for (int fn = 0; fn < 4; fn++) {
            const int n = ns * 64 + nw * 32 + fn * 8 + 2 * (lane & 3);
#pragma unroll
            for (int half = 0; half < 2; half++) {
                const int mrow = mw * 32 + fm * 16 + (lane >> 2) + half * 8;
                const long m = (long)mt * MTILE + mrow;
                float v0 = acc[fm][fn][half * 2 + 0];
                float v1 = acc[fm][fn][half * 2 + 1];
                if (mode == 1) {
                    float b0 = (n < 300) ? bias[n] : ((n == 300) ? bias2[0] : 0.f);
                    float b1 = (n + 1 < 300) ? bias[n + 1] : ((n + 1 == 301) ? bias2[1] : 0.f);
                    v0 += b0; v1 += b1;
                    if (n == 300) {
                        g_logits[m * 2 + 0] = v0;
                        g_logits[m * 2 + 1] = v1;
                    }
                    __nv_bfloat162 h = __floats2bfloat162_rn(v0, v1);
                    char* dst = (char*)g_a2 + (size_t)(mt * NCHK + ns) * A_CHT_B
                                + swz((uint32_t)(mrow * 128 + (n & 63) * 2));
                    *(__nv_bfloat162*)dst = h;
                } else {
                    if (n < 300) {  // n even => n <= 298
                        v0 += bias[n];
                        v1 += bias[n + 1];
                        *(__nv_bfloat162*)(g_cv + m * EMBED + n) =
                            __floats2bfloat162_rn(v0, v1);
                    }
                }
            }
        }
    }
}

// ---------------------------------------------------------------------------
// math helpers
// ---------------------------------------------------------------------------
__device__ __forceinline__ float softplus_f(float x) {
    float ax = fabsf(x);
    float r = log1pf(__expf(-ax));
    return (x > 0.f) ? x + r : r;
}
__device__ __forceinline__ float clip10(float x) { return fminf(fmaxf(x, -10.f), 10.f); }
__device__ __forceinline__ float warp_sum(float v) {
#pragma unroll
    for (int o = 16; o > 0; o >>= 1) v += __shfl_xor_sync(0xffffffffu, v, o);
    return v;
}

// ---------------------------------------------------------------------------
// Score: one warp per sample, full-ILP gathers, deterministic block partials.
// ---------------------------------------------------------------------------
__global__ __launch_bounds__(256)
void score_kernel(const int* __restrict__ ctx_ids,
                  const int* __restrict__ neg_ids,
                  const int* __restrict__ party,
                  const float* __restrict__ ctx_emb)
{
    const int warp = threadIdx.x >> 5;
    const int lane = threadIdx.x & 31;
    const int b    = blockIdx.x * 8 + warp;

    __shared__ float s_deno[8];
    __shared__ float s_cono[8];

    // center_v row (bf16), lane-strided
    float2 cv[5];
    const __nv_bfloat162* cvrow = (const __nv_bfloat162*)(g_cv + (long)b * EMBED);
#pragma unroll
    for (int j = 0; j < 5; j++) {
        int e2 = lane + j * 32;
        cv[j] = (e2 < 150) ? __bfloat1622float2(cvrow[e2]) : make_float2(0.f, 0.f);
    }

    const float2* rows[11];
    rows[0] = (const float2*)(ctx_emb + (long)ctx_ids[b] * EMBED);
#pragma unroll
    for (int k = 0; k < K_NEG; k++)
        rows[1 + k] = (const float2*)(ctx_emb + (long)neg_ids[b * K_NEG + k] * EMBED);

    float s[11];
#pragma unroll
    for (int r = 0; r < 11; r++) s[r] = 0.f;

#pragma unroll
    for (int j = 0; j < 5; j++) {
        int e2 = lane + j * 32;
        if (e2 < 150) {
#pragma unroll
            for (int r = 0; r < 11; r++) {
                float2 t = rows[r][e2];
                s[r] = fmaf(cv[j].x, t.x, fmaf(cv[j].y, t.y, s[r]));
            }
        }
    }

#pragma unroll
    for (int r = 0; r < 11; r++) s[r] = warp_sum(s[r]);

    float deno = softplus_f(-clip10(s[0]));
#pragma unroll
    for (int r = 1; r < 11; r++) deno += softplus_f(clip10(s[r]));

    float l0 = g_logits[b * 2 + 0];
    float l1 = g_logits[b * 2 + 1];
    int lab = party[b];
    float nll = softplus_f((lab == 0) ? (l1 - l0) : (l0 - l1));

    if (lane == 0) { s_deno[warp] = deno; s_cono[warp] = nll; }
    __syncthreads();
    if (threadIdx.x == 0) {
        float ds = 0.f, cs = 0.f;
#pragma unroll
        for (int w = 0; w < 8; w++) { ds += s_deno[w]; cs += s_cono[w]; }
        g_partial[blockIdx.x] = make_float2(ds, cs);
    }
}

// ---------------------------------------------------------------------------
// Finalize
// ---------------------------------------------------------------------------
__global__ __launch_bounds__(1024)
void finalize_kernel(float* __restrict__ out)
{
    __shared__ float sd[1024];
    __shared__ float sc[1024];
    float d = 0.f, c = 0.f;
    for (int i = threadIdx.x; i < NPART; i += 1024) {
        float2 p = g_partial[i];
        d += p.x; c += p.y;
    }
    sd[threadIdx.x] = d; sc[threadIdx.x] = c;
    __syncthreads();
    for (int s = 512; s > 0; s >>= 1) {
        if (threadIdx.x < s) {
            sd[threadIdx.x] += sd[threadIdx.x + s];
            sc[threadIdx.x] += sc[threadIdx.x + s];
        }
        __syncthreads();
    }
    if (threadIdx.x == 0) {
        float dn = sd[0] / (float)BATCH;
        float cn = sc[0] / (float)BATCH;
        dn = fminf(fmaxf(dn, EPS_F), 10.f);
        cn = fminf(fmaxf(cn, EPS_F), 10.f);
        out[0] = fmaxf(dn + cn, EPS_F);
        out[1] = dn;
        out[2] = cn;
    }
}

// ---------------------------------------------------------------------------
// kernel_launch
// ---------------------------------------------------------------------------
extern "C" void kernel_launch(void* const* d_in, const int* in_sizes, int n_in,
                              void* d_out, int out_size)
{
    const int*   center_ids = (const int*)  d_in[0];
    const int*   ctx_ids    = (const int*)  d_in[1];
    const int*   neg_ids    = (const int*)  d_in[2];
    const int*   party      = (const int*)  d_in[3];
    const float* center_emb = (const float*)d_in[4];
    const float* ctx_emb    = (const float*)d_in[5];
    const float* W_enc      = (const float*)d_in[6];
    const float* b_enc      = (const float*)d_in[7];
    const float* W_dec      = (const float*)d_in[8];
    const float* b_dec      = (const float*)d_in[9];
    const float* W_cls      = (const float*)d_in[10];
    const float* b_cls      = (const float*)d_in[11];
    float* out = (float*)d_out;

    int4 *a1, *a2, *w1, *w2;
    cudaGetSymbolAddress((void**)&a1, g_a1);
    cudaGetSymbolAddress((void**)&a2, g_a2);
    cudaGetSymbolAddress((void**)&w1, g_w1);
    cudaGetSymbolAddress((void**)&w2, g_w2);

    // prepass conversions
    conv_w_kernel<<<(2 * NSPLIT * NCHK * 64 * 8 + 255) / 256, 256>>>(W_enc, W_cls, W_dec);
    conv_a_kernel<<<BATCH * 40 / 256, 256>>>(center_emb, center_ids);

    // GEMM1: [enc | logits] = gather(center_emb) @ [W_enc; W_cls]^T
    gemm_kernel<<<dim3(NSPLIT, MTILES), 256>>>(a1, w1, b_enc, b_cls, 1);
    // GEMM2: cv = enc @ W_dec^T + b_dec
    gemm_kernel<<<dim3(NSPLIT, MTILES), 256>>>(a2, w2, b_dec, nullptr, 2);

    // scoring + reduction
    score_kernel<<<NPART, 256>>>(ctx_ids, neg_ids, party, ctx_emb);
    finalize_kernel<<<1, 1024>>>(out);
}

// round 17
// speedup vs baseline: 1.2589x; 1.0075x over previous
#include <cuda_runtime.h>
#include <cuda_bf16.h>
#include <math.h>
#include <stdint.h>

// ---------------- problem constants ----------------
#define VOCAB   100000
#define EMBED   300
#define HIDDEN  300
#define BATCH   32768
#define K_NEG   10
#define EPS_F   1e-5f

// ---------------- GEMM geometry ----------------
#define MTILE    128
#define MTILES   (BATCH / MTILE)        // 256
#define NSPLIT   5                      // N padded to 320, 64 per split
#define NCHK     5                      // K padded to 320, 64 per chunk
#define A_CHT_B  16384                  // A chunk tile: 128 rows * 128 B
#define A_CHT_I4 1024
#define B_CHT_B  8192                   // B chunk tile: 64 rows * 128 B
#define B_CHT_I4 512

#define NPART     1024                  // 32 samples per score block
#define CW_BLOCKS 100                   // conv_w portion of merged conv launch
#define CA_BLOCKS (BATCH * 40 / 256)    // 5120

// ---------------- scratch (device globals; no allocation allowed) ----------------
__device__ int4  g_a1[MTILES * NCHK * A_CHT_I4];   // gathered center_emb, bf16 swizzled
__device__ int4  g_a2[MTILES * NCHK * A_CHT_I4];   // enc, bf16 swizzled (GEMM1 epilogue)
__device__ int4  g_w1[NSPLIT * NCHK * B_CHT_I4];   // [W_enc; W_cls; 0] bf16 swizzled
__device__ int4  g_w2[NSPLIT * NCHK * B_CHT_I4];   // [W_dec; 0] bf16 swizzled
__device__ float g_logits[BATCH * 2];
__device__ __nv_bfloat16 g_cv[BATCH * EMBED];      // center_v in bf16
__device__ float2 g_partial[NPART];

// ---------------- small device helpers ----------------
__device__ __forceinline__ uint32_t swz(uint32_t o) { return o ^ ((o >> 3) & 0x70); }

__device__ __forceinline__ uint32_t smem_u32(const void* p) {
    uint32_t a;
    asm("{ .reg .u64 t; cvta.to.shared.u64 t, %1; cvt.u32.u64 %0, t; }" : "=r"(a) : "l"(p));
    return a;
}
__device__ __forceinline__ void ldm_x4(uint32_t* r, uint32_t addr) {
    asm volatile("ldmatrix.sync.aligned.m8n8.x4.shared.b16 {%0,%1,%2,%3}, [%4];"
                 : "=r"(r[0]), "=r"(r[1]), "=r"(r[2]), "=r"(r[3]) : "r"(addr));
}
__device__ __forceinline__ void mma_16816(float* c, const uint32_t* a, const uint32_t* b) {
    asm volatile("mma.sync.aligned.m16n8k16.row.col.f32.bf16.bf16.f32 "
                 "{%0,%1,%2,%3}, {%4,%5,%6,%7}, {%8,%9}, {%0,%1,%2,%3};"
                 : "+f"(c[0]), "+f"(c[1]), "+f"(c[2]), "+f"(c[3])
                 : "r"(a[0]), "r"(a[1]), "r"(a[2]), "r"(a[3]), "r"(b[0]), "r"(b[1]));
}
__device__ __forceinline__ void cp_async16(uint32_t dst, const void* src) {
    asm volatile("cp.async.cg.shared.global [%0], [%1], 16;" :: "r"(dst), "l"(src));
}
__device__ __forceinline__ void cp_commit() {
    asm volatile("cp.async.commit_group;" ::: "memory");
}
__device__ __forceinline__ void cp_wait0() {
    asm volatile("cp.async.wait_group 0;" ::: "memory");
}

__device__ __forceinline__ int4 pack8_bf16(const float* v) {
    union { __nv_bfloat162 h[4]; int4 q; } u;
#pragma unroll
    for (int j = 0; j < 4; j++) u.h[j] = __floats2bfloat162_rn(v[2 * j], v[2 * j + 1]);
    return u.q;
}

// ---------------------------------------------------------------------------
// Merged prepass: blocks [0, CW_BLOCKS) convert weights, rest gather A.
// ---------------------------------------------------------------------------
__global__ __launch_bounds__(256)
void conv_kernel(const float* __restrict__ emb, const int* __restrict__ ids,
                 const float* __restrict__ Wenc, const float* __restrict__ Wcls,
                 const float* __restrict__ Wdec)
{
    if (blockIdx.x < CW_BLOCKS) {
        // ---- conv_w: 2 * 12800 groups of 8 ----
        const int PER_MODE = NSPLIT * NCHK * 64 * 8;
        int idx = blockIdx.x * 256 + threadIdx.x;
        int mode = idx / PER_MODE;
        int rem  = idx - mode * PER_MODE;
        int col8 = rem & 7;
        int r    = (rem >> 3) & 63;
        int t    = rem >> 9;
        int c    = t % NCHK;
        int s    = t / NCHK;
        int n  = s * 64 + r;
        int k0 = c * 64 + col8 * 8;

        const float* row = nullptr;
        if (n < 300) row = (mode == 0 ? Wenc : Wdec) + (long)n * 300;
        else if (mode == 0 && n < 302) row = Wcls + (long)(n - 300) * 300;

        float v[8];
#pragma unroll
        for (int j = 0; j < 8; j++) v[j] = 0.f;
        if (row) {
            if (k0 + 8 <= 300) {
                float4 f0 = *(const float4*)(row + k0);
                float4 f1 = *(const float4*)(row + k0 + 4);
                v[0]=f0.x; v[1]=f0.y; v[2]=f0.z; v[3]=f0.w;
                v[4]=f1.x; v[5]=f1.y; v[6]=f1.z; v[7]=f1.w;
            } else if (k0 < 300) {
                float4 f0 = *(const float4*)(row + k0);
                v[0]=f0.x; v[1]=f0.y; v[2]=f0.z; v[3]=f0.w;
            }
        }
        int4* gw = (mode == 0) ? g_w1 : g_w2;
        char* base = (char*)gw + (size_t)(s * NCHK + c) * B_CHT_B;
        *(int4*)(base + swz((uint32_t)(r * 128 + (k0 & 63) * 2))) = pack8_bf16(v);
    } else {
        // ---- conv_a: gather center_emb -> bf16 swizzled chunk tiles ----
        int idx = (blockIdx.x - CW_BLOCKS) * 256 + threadIdx.x;
        int m  = idx / 40;
        int g  = idx - m * 40;
        int k0 = g * 8;
        const float* row = emb + (long)ids[m] * EMBED;

        float v[8];
        if (k0 + 8 <= EMBED) {
            float4 f0 = *(const float4*)(row + k0);
            float4 f1 = *(const float4*)(row + k0 + 4);
            v[0]=f0.x; v[1]=f0.y; v[2]=f0.z; v[3]=f0.w;
            v[4]=f1.x; v[5]=f1.y; v[6]=f1.z; v[7]=f1.w;
        } else if (k0 < EMBED) {      // k0 == 296
            float4 f0 = *(const float4*)(row + k0);
            v[0]=f0.x; v[1]=f0.y; v[2]=f0.z; v[3]=f0.w;
            v[4]=v[5]=v[6]=v[7]=0.f;
        } else {
#pragma unroll
            for (int j = 0; j < 8; j++) v[j] = 0.f;
        }

        int mt = m >> 7, mrow = m & 127, ch = k0 >> 6, col0 = k0 & 63;
        char* base = (char*)g_a1 + (size_t)(mt * NCHK + ch) * A_CHT_B;
        *(int4*)(base + swz((uint32_t)(mrow * 128 + col0 * 2))) = pack8_bf16(v);
    }
}

// ---------------------------------------------------------------------------
// bf16 HMMA GEMM, cp.async double-buffered, ONE sync per chunk.
// mode 1: epilogue -> g_a2 (bf16 swizzled A-layout) + g_logits (+b_cls)
// mode 2: epilogue -> g_cv bf16 (+b_dec)
// ---------------------------------------------------------------------------
__global__ __launch_bounds__(256)
void gemm_kernel(const int4* __restrict__ A, const int4* __restrict__ B,
                 const float* __restrict__ bias, const float* __restrict__ bias2,
                 int mode)
{
    __shared__ int4 smem[2 * A_CHT_I4 + 2 * B_CHT_I4];   // 48 KB
    const uint32_t sbase = smem_u32(smem);
    const uint32_t sAoff[2] = { 0u, (uint32_t)A_CHT_B };
    const uint32_t sBoff[2] = { 2u * A_CHT_B, 2u * A_CHT_B + B_CHT_B };

    const int tid  = threadIdx.x;
    const int wid  = tid >> 5;
    const int lane = tid & 31;
    const int mt = blockIdx.y;
    const int ns = blockIdx.x;
    const int mw = wid & 3;
    const int nw = wid >> 2;

    float acc[2][4][4];
#pragma unroll
    for (int i = 0; i < 2; i++)
#pragma unroll
        for (int j = 0; j < 4; j++)
#pragma unroll
            for (int q = 0; q < 4; q++) acc[i][j][q] = 0.f;

    const int4* Abase = A + (size_t)mt * NCHK * A_CHT_I4;
    const int4* Bbase = B + (size_t)ns * NCHK * B_CHT_I4;

    const uint32_t a_row  = mw * 32 + (lane & 15);
    const uint32_t a_kb   = (lane >> 4) * 16;
    const uint32_t b_row  = nw * 32 + (lane & 7) + ((lane >> 4) << 3);
    const uint32_t b_kb   = ((lane >> 3) & 1) * 16;

#define PREFETCH(c, buf) do {                                                  \
        const int4* _as = Abase + (c) * A_CHT_I4;                              \
        uint32_t _da = sbase + sAoff[buf];                                     \
        _Pragma("unroll")                                                      \
        for (int _i = 0; _i < 4; _i++)                                         \
            cp_async16(_da + (uint32_t)(tid + _i * 256) * 16u, _as + tid + _i * 256); \
        const int4* _bs = Bbase + (c) * B_CHT_I4;                              \
        uint32_t _db = sbase + sBoff[buf];                                     \
        _Pragma("unroll")                                                      \
        for (int _i = 0; _i < 2; _i++)                                         \
            cp_async16(_db + (uint32_t)(tid + _i * 256) * 16u, _bs + tid + _i * 256); \
        cp_commit();                                                           \
    } while (0)

    PREFETCH(0, 0);

    for (int c = 0; c < NCHK; c++) {
        cp_wait0();
        __syncthreads();
        if (c + 1 < NCHK) PREFETCH(c + 1, (c + 1) & 1);

        const uint32_t aB = sbase + sAoff[c & 1];
        const uint32_t bB = sbase + sBoff[c & 1];
#pragma unroll
        for (int ks = 0; ks < 4; ks++) {
            const uint32_t kb = ks * 32;
            uint32_t a[2][4];
#pragma unroll
            for (int fm = 0; fm < 2; fm++)
                ldm_x4(a[fm], aB + swz((a_row + fm * 16) * 128 + kb + a_kb));
#pragma unroll
            for (int p = 0; p < 2; p++) {
                uint32_t bq[4];
                ldm_x4(bq, bB + swz((b_row + p * 16) * 128 + kb + b_kb));
                mma_16816(acc[0][2 * p + 0], a[0], bq + 0);
                mma_16816(acc[1][2 * p + 0], a[1], bq + 0);
                mma_16816(acc[0][2 * p + 1], a[0], bq + 2);
                mma_16816(acc[1][2 * p + 1], a[1], bq + 2);
            }
        }
    }
#undef PREFETCH

    // ---- epilogue ----
#pragma unroll
    for (int fm = 0; fm < 2; fm++) {
#pragma unroll
        for (int fn = 0; fn < 4; fn++) {
            const int n = ns * 64 + nw * 32 + fn * 8 + 2 * (lane & 3);
#pragma unroll
            for (int half = 0; half < 2; half++) {
                const int mrow = mw * 32 + fm * 16 + (lane >> 2) + half * 8;
                const long m = (long)mt * MTILE + mrow;
                float v0 = acc[fm][fn][half * 2 + 0];
                float v1 = acc[fm][fn][half * 2 + 1];
                if (mode == 1) {
                    float b0 = (n < 300) ? bias[n] : ((n == 300) ? bias2[0] : 0.f);
                    float b1 = (n + 1 < 300) ? bias[n + 1] : ((n + 1 == 301) ? bias2[1] : 0.f);
                    v0 += b0; v1 += b1;
                    if (n == 300) {
                        g_logits[m * 2 + 0] = v0;
                        g_logits[m * 2 + 1] = v1;
                    }
                    __nv_bfloat162 h = __floats2bfloat162_rn(v0, v1);
                    char* dst = (char*)g_a2 + (size_t)(mt * NCHK + ns) * A_CHT_B
                                + swz((uint32_t)(mrow * 128 + (n & 63) * 2));
                    *(__nv_bfloat162*)dst = h;
                } else {
                    if (n < 300) {
                        v0 += bias[n];
                        v1 += bias[n + 1];
                        *(__nv_bfloat162*)(g_cv + m * EMBED + n) =
                            __floats2bfloat162_rn(v0, v1);
                    }
                }
            }
        }
    }
}

// ---------------------------------------------------------------------------
// math helpers
// ---------------------------------------------------------------------------
__device__ __forceinline__ float softplus_f(float x) {
    float ax = fabsf(x);
    float r = log1pf(__expf(-ax));
    return (x > 0.f) ? x + r : r;
}
__device__ __forceinline__ float clip10(float x) { return fminf(fmaxf(x, -10.f), 10.f); }
__device__ __forceinline__ float warp_sum(float v) {
#pragma unroll
    for (int o = 16; o > 0; o >>= 1) v += __shfl_xor_sync(0xffffffffu, v, o);
    return v;
}

// ---------------------------------------------------------------------------
// Score: one warp = 4 samples (serial), float4 gathers (3 per row, 1 pred).
// Block covers 32 samples -> NPART = 1024 partials.
// ---------------------------------------------------------------------------
__global__ __launch_bounds__(256)
void score_kernel(const int* __restrict__ ctx_ids,
                  const int* __restrict__ neg_ids,
                  const int* __restrict__ party,
                  const float* __restrict__ ctx_emb)
{
    const int warp = threadIdx.x >> 5;
    const int lane = threadIdx.x & 31;
    const int b0   = blockIdx.x * 32 + warp * 4;

    __shared__ float s_deno[8];
    __shared__ float s_cono[8];

    float dacc = 0.f, cacc = 0.f;

#pragma unroll 1
    for (int it = 0; it < 4; it++) {
        const int b = b0 + it;

        // cv: bf16 row, 4 elements per slot (8B loads)
        float4 cv[3];
        const uint2* cvrow = (const uint2*)(g_cv + (size_t)b * EMBED);
#pragma unroll
        for (int j = 0; j < 3; j++) {
            int e4 = lane + j * 32;
            if (e4 < 75) {
                uint2 u = cvrow[e4];
                float2 f0 = __bfloat1622float2(*(__nv_bfloat162*)&u.x);
                float2 f1 = __bfloat1622float2(*(__nv_bfloat162*)&u.y);
                cv[j] = make_float4(f0.x, f0.y, f1.x, f1.y);
            } else {
                cv[j] = make_float4(0.f, 0.f, 0.f, 0.f);
            }
        }

        const float4* rows[11];
        rows[0] = (const float4*)(ctx_emb + (size_t)ctx_ids[b] * EMBED);
#pragma unroll
        for (int k = 0; k < K_NEG; k++)
            rows[1 + k] = (const float4*)(ctx_emb + (size_t)neg_ids[b * K_NEG + k] * EMBED);

        float s[11];
#pragma unroll
        for (int r = 0; r < 11; r++) s[r] = 0.f;

#pragma unroll
        for (int j = 0; j < 3; j++) {
            int e4 = lane + j * 32;
            if (e4 < 75) {
#pragma unroll
                for (int r = 0; r < 11; r++) {
                    float4 t = rows[r][e4];
                    s[r] = fmaf(cv[j].x, t.x,
                           fmaf(cv[j].y, t.y,
                           fmaf(cv[j].z, t.z,
                           fmaf(cv[j].w, t.w, s[r]))));
                }
            }
        }

#pragma unroll
        for (int r = 0; r < 11; r++) s[r] = warp_sum(s[r]);

        dacc += softplus_f(-clip10(s[0]));
#pragma unroll
        for (int r = 1; r < 11; r++) dacc += softplus_f(clip10(s[r]));

        float l0 = g_logits[b * 2 + 0];
        float l1 = g_logits[b * 2 + 1];
        cacc += softplus_f((party[b] == 0) ? (l1 - l0) : (l0 - l1));
    }

    if (lane == 0) { s_deno[warp] = dacc; s_cono[warp] = cacc; }
    __syncthreads();
    if (threadIdx.x == 0) {
        float ds = 0.f, cs = 0.f;
#pragma unroll
        for (int w = 0; w < 8; w++) { ds += s_deno[w]; cs += s_cono[w]; }
        g_partial[blockIdx.x] = make_float2(ds, cs);
    }
}

// ---------------------------------------------------------------------------
// Finalize (1024 partials)
// ---------------------------------------------------------------------------
__global__ __launch_bounds__(256)
void finalize_kernel(float* __restrict__ out)
{
    __shared__ float sd[256];
    __shared__ float sc[256];
    float d = 0.f, c = 0.f;
#pragma unroll
    for (int i = threadIdx.x; i < NPART; i += 256) {
        float2 p = g_partial[i];
        d += p.x; c += p.y;
    }
    sd[threadIdx.x] = d; sc[threadIdx.x] = c;
    __syncthreads();
    for (int s = 128; s > 0; s >>= 1) {
        if (threadIdx.x < s) {
            sd[threadIdx.x] += sd[threadIdx.x + s];
            sc[threadIdx.x] += sc[threadIdx.x + s];
        }
        __syncthreads();
    }
    if (threadIdx.x == 0) {
        float dn = sd[0] / (float)BATCH;
        float cn = sc[0] / (float)BATCH;
        dn = fminf(fmaxf(dn, EPS_F), 10.f);
        cn = fminf(fmaxf(cn, EPS_F), 10.f);
        out[0] = fmaxf(dn + cn, EPS_F);
        out[1] = dn;
        out[2] = cn;
    }
}

// ---------------------------------------------------------------------------
// kernel_launch
// ---------------------------------------------------------------------------
extern "C" void kernel_launch(void* const* d_in, const int* in_sizes, int n_in,
                              void* d_out, int out_size)
{
    const int*   center_ids = (const int*)  d_in[0];
    const int*   ctx_ids    = (const int*)  d_in[1];
    const int*   neg_ids    = (const int*)  d_in[2];
    const int*   party      = (const int*)  d_in[3];
    const float* center_emb = (const float*)d_in[4];
    const float* ctx_emb    = (const float*)d_in[5];
    const float* W_enc      = (const float*)d_in[6];
    const float* b_enc      = (const float*)d_in[7];
    const float* W_dec      = (const float*)d_in[8];
    const float* b_dec      = (const float*)d_in[9];
    const float* W_cls      = (const float*)d_in[10];
    const float* b_cls      = (const float*)d_in[11];
    float* out = (float*)d_out;

    int4 *a1, *a2, *w1, *w2;
    cudaGetSymbolAddress((void**)&a1, g_a1);
    cudaGetSymbolAddress((void**)&a2, g_a2);
    cudaGetSymbolAddress((void**)&w1, g_w1);
    cudaGetSymbolAddress((void**)&w2, g_w2);

    // merged prepass: weights + gathered A
    conv_kernel<<<CW_BLOCKS + CA_BLOCKS, 256>>>(center_emb, center_ids,
                                                W_enc, W_cls, W_dec);

    // GEMM1: [enc | logits] = gather(center_emb) @ [W_enc; W_cls]^T
    gemm_kernel<<<dim3(NSPLIT, MTILES), 256>>>(a1, w1, b_enc, b_cls, 1);
    // GEMM2: cv = enc @ W_dec^T + b_dec
    gemm_kernel<<<dim3(NSPLIT, MTILES), 256>>>(a2, w2, b_dec, nullptr, 2);

    // scoring + reduction
    score_kernel<<<NPART, 256>>>(ctx_ids, neg_ids, party, ctx_emb);
    finalize_kernel<<<1, 256>>>(out);
}